// round 5
// baseline (speedup 1.0000x reference)
#include <cuda_runtime.h>
#include <cstdint>

#define NB 8
#define NQ 100000
#define NC 10
#define NPB (NQ*NC)          // 1,000,000 logits per batch
#define NP 20
#define TOPK 100
#define BINS 4096
#define BIN_SHIFT 20
#define CAP 32768
#define KEEPMAX 1024
#define KEY0 0xC0400000u     // sortable key of +3.0f (speculative collect threshold)

// ---- scratch (no allocations allowed) ----
__device__ unsigned int       g_hist[NB][BINS];
__device__ int                g_cnt[NB];
__device__ unsigned int       g_cutkey[NB];
__device__ int                g_fb[NB];
__device__ unsigned long long g_cand[NB][CAP];

__device__ __forceinline__ unsigned int f2key(float f) {
    unsigned int u = __float_as_uint(f);
    return (u & 0x80000000u) ? ~u : (u | 0x80000000u);
}
__device__ __forceinline__ float key2f(unsigned int k) {
    unsigned int u = (k & 0x80000000u) ? (k & 0x7FFFFFFFu) : ~k;
    return __uint_as_float(u);
}

__global__ void zero_k() {
    int i = blockIdx.x * blockDim.x + threadIdx.x;
    int stride = gridDim.x * blockDim.x;
    unsigned int* h = (unsigned int*)g_hist;
    for (int t = i; t < NB * BINS; t += stride) h[t] = 0u;
    if (i < NB) g_cnt[i] = 0;
}

// Pass 1: histogram of keys + speculative candidate collection (logit >= 3.0)
__global__ void hist_k(const float* __restrict__ cls) {
    __shared__ unsigned int sh[BINS];
    const int b = blockIdx.y;
    for (int t = threadIdx.x; t < BINS; t += blockDim.x) sh[t] = 0u;
    __syncthreads();

    const float4* src = (const float4*)(cls + (size_t)b * NPB);
    const int n4 = NPB / 4;
    const int stride = gridDim.x * blockDim.x;
    for (int i = blockIdx.x * blockDim.x + threadIdx.x; i < n4; i += stride) {
        float4 v = src[i];
        float vals[4] = {v.x, v.y, v.z, v.w};
#pragma unroll
        for (int k = 0; k < 4; k++) {
            unsigned int key = f2key(vals[k]);
            atomicAdd(&sh[key >> BIN_SHIFT], 1u);
            if (key >= KEY0) {
                int pos = atomicAdd(&g_cnt[b], 1);
                if (pos < CAP) {
                    unsigned int idx = 4u * (unsigned int)i + (unsigned int)k;
                    g_cand[b][pos] =
                        ((unsigned long long)key << 32) | (unsigned int)(~idx);
                }
            }
        }
    }
    __syncthreads();
    for (int t = threadIdx.x; t < BINS; t += blockDim.x)
        if (sh[t]) atomicAdd(&g_hist[b][t], sh[t]);
}

// Pass 2: exact cutoff bin (largest bin with suffix-count >= TOPK), set fallback flag
__global__ void select_k() {
    const int b = blockIdx.x;
    __shared__ unsigned int chunkSum[256];
    __shared__ unsigned int suff[256];
    const int tid = threadIdx.x;
    const int base = tid * 16;
    unsigned int h[16];
    unsigned int s = 0;
#pragma unroll
    for (int j = 0; j < 16; j++) { h[j] = g_hist[b][base + j]; s += h[j]; }
    chunkSum[tid] = s;
    __syncthreads();
    if (tid == 0) {
        unsigned int acc = 0;
        for (int t = 255; t >= 0; t--) { acc += chunkSum[t]; suff[t] = acc; }
    }
    __syncthreads();
    unsigned int above = (tid == 255) ? 0u : suff[tid + 1];
    if (above < TOPK && suff[tid] >= TOPK) {   // exactly one thread
        unsigned int acc = above;
        int cut = base;
        for (int j = 15; j >= 0; j--) {
            acc += h[j];
            if (acc >= TOPK) { cut = base + j; break; }
        }
        unsigned int ck = (unsigned int)cut << BIN_SHIFT;
        g_cutkey[b] = ck;
        int cnt = g_cnt[b];
        int fb;
        if (cnt > CAP)      { g_cnt[b] = 0; fb = 2; }   // overflow: recollect all
        else if (ck < KEY0) { fb = 1; }                 // speculative thr too high
        else                { fb = 0; }                 // fast path: done
        g_fb[b] = fb;
    }
}

// Pass 3 (rare): fallback collection. Early-exits on the fast path.
__global__ void collect_k(const float* __restrict__ cls) {
    const int b = blockIdx.y;
    const int fb = g_fb[b];
    if (fb == 0) return;
    const unsigned int lo = g_cutkey[b];
    const float4* src = (const float4*)(cls + (size_t)b * NPB);
    const int n4 = NPB / 4;
    const int stride = gridDim.x * blockDim.x;
    for (int i = blockIdx.x * blockDim.x + threadIdx.x; i < n4; i += stride) {
        float4 v = src[i];
        float vals[4] = {v.x, v.y, v.z, v.w};
#pragma unroll
        for (int k = 0; k < 4; k++) {
            unsigned int key = f2key(vals[k]);
            bool take = (fb == 2) ? (key >= lo) : (key >= lo && key < KEY0);
            if (take) {
                int pos = atomicAdd(&g_cnt[b], 1);
                if (pos < CAP) {
                    unsigned int idx = 4u * (unsigned int)i + (unsigned int)k;
                    g_cand[b][pos] =
                        ((unsigned long long)key << 32) | (unsigned int)(~idx);
                }
            }
        }
    }
}

// Pass 4: exact top-100 via rank-by-count, thresh/range masks, denorm + write
__global__ void final_k(const float* __restrict__ bbox,
                        const float* __restrict__ pts,
                        float* __restrict__ out) {
    const int b = blockIdx.x;
    __shared__ unsigned long long arr[KEEPMAX];
    __shared__ unsigned long long topc[TOPK];
    __shared__ int nkeep;
    __shared__ int mode_s;
    __shared__ float thr_s;

    if (threadIdx.x == 0) nkeep = 0;
    if (threadIdx.x < TOPK) topc[threadIdx.x] = 0ULL;
    __syncthreads();

    const int cnt = min(g_cnt[b], CAP);
    const unsigned int ck = g_cutkey[b];
    for (int i = threadIdx.x; i < cnt; i += blockDim.x) {
        unsigned long long c = g_cand[b][i];
        if ((unsigned int)(c >> 32) >= ck) {
            int p = atomicAdd(&nkeep, 1);
            if (p < KEEPMAX) arr[p] = c;
        }
    }
    __syncthreads();
    const int n = min(nkeep, KEEPMAX);

    // rank = #elements strictly greater (composites distinct -> unique ranks)
    for (int i = threadIdx.x; i < n; i += blockDim.x) {
        unsigned long long c = arr[i];
        int rank = 0;
        for (int j = 0; j < n; j++) rank += (arr[j] > c);
        if (rank < TOPK) topc[rank] = c;
    }
    __syncthreads();

    if (threadIdx.x == 0) {
        float maxs = 0.f;
        if (n > 0) {
            float f = key2f((unsigned int)(topc[0] >> 32));
            maxs = 1.f / (1.f + expf(-f));
        }
        int mode; float thr = 0.1f;
        if (maxs > 0.1f) mode = 0;
        else {
            float tmp = 0.1f; mode = 2;
            while (true) {
                tmp *= 0.9f;
                if (tmp < 0.01f) { mode = 2; break; }
                if (maxs >= tmp) { mode = 1; thr = tmp; break; }
            }
        }
        mode_s = mode; thr_s = thr;
    }
    __syncthreads();

    // output layout (float32, tuple order, C-contiguous each):
    float* oBox   = out;                       // [NB][TOPK][4]
    float* oScore = out + NB * TOPK * 4;       // [NB][TOPK]
    float* oLabel = oScore + NB * TOPK;        // [NB][TOPK]
    float* oPts   = oLabel + NB * TOPK;        // [NB][TOPK][NP][2]
    float* oMask  = oPts + NB * TOPK * NP * 2; // [NB][TOPK]

    for (int r = threadIdx.x; r < TOPK; r += blockDim.x) {
        unsigned long long c = topc[r];
        const bool valid = (r < n);
        float score = 0.f, x1 = 0.f, y1 = 0.f, x2 = 0.f, y2 = 0.f;
        int label = 0, q = 0;
        bool mask = false;
        if (valid) {
            unsigned int key = (unsigned int)(c >> 32);
            unsigned int idx = ~(unsigned int)(c & 0xFFFFFFFFu);
            float f = key2f(key);
            score = 1.f / (1.f + expf(-f));
            label = (int)(idx % NC);
            q     = (int)(idx / NC);
            const float* bb = bbox + ((size_t)b * NQ + q) * 4;
            float cx = bb[0], cy = bb[1], w = bb[2], h = bb[3];
            x1 = (cx - w * 0.5f) * 30.f - 15.f;
            y1 = (cy - h * 0.5f) * 60.f - 30.f;
            x2 = (cx + w * 0.5f) * 30.f - 15.f;
            y2 = (cy + h * 0.5f) * 60.f - 30.f;
            bool rmask = x1 >= -20.f && y1 >= -35.f && x2 >= -20.f && y2 >= -35.f
                      && x1 <=  20.f && y1 <=  35.f && x2 <=  20.f && y2 <=  35.f;
            bool tm = (mode_s == 0) ? (score > 0.1f)
                    : (mode_s == 1) ? (score >= thr_s) : true;
            mask = rmask && tm;
        }
        const size_t ob = (size_t)b * TOPK + r;
        oBox[ob * 4 + 0] = mask ? x1 : 0.f;
        oBox[ob * 4 + 1] = mask ? y1 : 0.f;
        oBox[ob * 4 + 2] = mask ? x2 : 0.f;
        oBox[ob * 4 + 3] = mask ? y2 : 0.f;
        oScore[ob] = mask ? score : 0.f;
        oLabel[ob] = mask ? (float)label : 0.f;
        oMask[ob]  = mask ? 1.f : 0.f;
        const float* pp = pts + ((size_t)b * NQ + q) * (NP * 2);
#pragma unroll
        for (int j = 0; j < NP; j++) {
            float vx = 0.f, vy = 0.f;
            if (valid) { vx = pp[2 * j]; vy = pp[2 * j + 1]; }
            vx = vx * 30.f - 15.f;
            vy = vy * 60.f - 30.f;
            oPts[ob * (NP * 2) + 2 * j]     = mask ? vx : 0.f;
            oPts[ob * (NP * 2) + 2 * j + 1] = mask ? vy : 0.f;
        }
    }
}

extern "C" void kernel_launch(void* const* d_in, const int* in_sizes, int n_in,
                              void* d_out, int out_size) {
    const float* cls  = (const float*)d_in[0];   // [8,100000,10]
    const float* bbox = (const float*)d_in[1];   // [8,100000,4]
    const float* pts  = (const float*)d_in[2];   // [8,100000,20,2]
    float* out = (float*)d_out;

    zero_k<<<64, 512>>>();
    dim3 grid(120, NB);
    hist_k<<<grid, 256>>>(cls);
    select_k<<<NB, 256>>>();
    collect_k<<<grid, 256>>>(cls);
    final_k<<<NB, 512>>>(bbox, pts, out);
}

// round 6
// speedup vs baseline: 1.0544x; 1.0544x over previous
#include <cuda_runtime.h>
#include <cstdint>

#define NB 8
#define NQ 100000
#define NC 10
#define NPB (NQ*NC)          // 1,000,000 logits per batch
#define NP 20
#define TOPK 100
#define CAP 32768
#define KEEPMAX 2048
#define KEY0 0xC0400000u     // sortable key of +3.0f (speculative collect threshold)
#define BINS 4096
#define BIN_SHIFT 20

// ---- scratch (no allocations allowed) ----
__device__ int                g_cnt[NB];          // zero-initialized; final_k resets it
__device__ unsigned long long g_cand[NB][CAP];

__device__ __forceinline__ unsigned int f2key(float f) {
    unsigned int u = __float_as_uint(f);
    return (u & 0x80000000u) ? ~u : (u | 0x80000000u);
}
__device__ __forceinline__ float key2f(unsigned int k) {
    unsigned int u = (k & 0x80000000u) ? (k & 0x7FFFFFFFu) : ~k;
    return __uint_as_float(u);
}

__device__ __forceinline__ void push_cand(int b, unsigned int key, unsigned int lidx) {
    int pos = atomicAdd(&g_cnt[b], 1);
    if (pos < CAP)
        g_cand[b][pos] = ((unsigned long long)key << 32) | (unsigned int)(~lidx);
}

// ---- Pass 1: single streaming scan, speculative candidate collection only ----
__global__ void scan_k(const float* __restrict__ cls) {
    const float4* src = (const float4*)cls;
    const unsigned int n4 = (unsigned int)NB * (NPB / 4);
    const unsigned int stride = gridDim.x * blockDim.x;
    for (unsigned int i = blockIdx.x * blockDim.x + threadIdx.x; i < n4; i += stride) {
        float4 v = __ldcs(src + i);
        unsigned int k0 = f2key(v.x), k1 = f2key(v.y), k2 = f2key(v.z), k3 = f2key(v.w);
        if ((k0 >= KEY0) | (k1 >= KEY0) | (k2 >= KEY0) | (k3 >= KEY0)) {
            int b = (int)(i / (NPB / 4));
            unsigned int e = i * 4u - (unsigned int)b * (unsigned int)NPB;
            if (k0 >= KEY0) push_cand(b, k0, e + 0);
            if (k1 >= KEY0) push_cand(b, k1, e + 1);
            if (k2 >= KEY0) push_cand(b, k2, e + 2);
            if (k3 >= KEY0) push_cand(b, k3, e + 3);
        }
    }
}

// find largest bin such that count(keys >= bin<<SHIFT) >= TOPK, from shared hist.
// blockDim.x must be 512 (512 threads x 8 bins = 4096).
__device__ unsigned int find_cut(const unsigned int* hist,
                                 unsigned int* chunk, unsigned int* suff,
                                 unsigned int* out_cut) {
    const int tid = threadIdx.x;
    const int base = tid * 8;
    unsigned int h[8];
    unsigned int s = 0;
#pragma unroll
    for (int j = 0; j < 8; j++) { h[j] = hist[base + j]; s += h[j]; }
    chunk[tid] = s;
    __syncthreads();
    if (tid == 0) {
        unsigned int acc = 0;
        for (int t = 511; t >= 0; t--) { acc += chunk[t]; suff[t] = acc; }
    }
    __syncthreads();
    unsigned int above = (tid == 511) ? 0u : suff[tid + 1];
    if (above < TOPK && suff[tid] >= TOPK) {   // exactly one thread
        unsigned int acc = above;
        int cut = base;
        for (int j = 7; j >= 0; j--) {
            acc += h[j];
            if (acc >= TOPK) { cut = base + j; break; }
        }
        *out_cut = (unsigned int)cut << BIN_SHIFT;
    }
    __syncthreads();
    return *out_cut;
}

// ---- Pass 2: exact cutoff from candidates, top-100, masks, denorm, write ----
__global__ void __launch_bounds__(512) final_k(const float* __restrict__ cls,
                                               const float* __restrict__ bbox,
                                               const float* __restrict__ pts,
                                               float* __restrict__ out) {
    __shared__ unsigned int hist[BINS];
    __shared__ unsigned int chunk[512];
    __shared__ unsigned int suff[512];
    __shared__ unsigned int cut_s;
    __shared__ unsigned long long arr[KEEPMAX];
    __shared__ unsigned long long topc[TOPK];
    __shared__ int nkeep;
    __shared__ int mode_s;
    __shared__ float thr_s;

    const int b = blockIdx.x;
    const int tid = threadIdx.x;

    int cnt = g_cnt[b];
    if (cnt < TOPK || cnt > CAP) {
        // ---- fallback (never taken on this data): exact recollect ----
        if (tid == 0) g_cnt[b] = 0;
        for (int t = tid; t < BINS; t += blockDim.x) hist[t] = 0u;
        __syncthreads();
        const float* base = cls + (size_t)b * NPB;
        for (int i = tid; i < NPB; i += blockDim.x)
            atomicAdd(&hist[f2key(base[i]) >> BIN_SHIFT], 1u);
        __syncthreads();
        unsigned int ck = find_cut(hist, chunk, suff, &cut_s);
        for (int i = tid; i < NPB; i += blockDim.x) {
            unsigned int key = f2key(base[i]);
            if (key >= ck) push_cand(b, key, (unsigned int)i);
        }
        __syncthreads();
        cnt = g_cnt[b];
    }
    cnt = min(cnt, CAP);

    // ---- histogram over candidates only (~1.3k) ----
    for (int t = tid; t < BINS; t += blockDim.x) hist[t] = 0u;
    __syncthreads();
    for (int i = tid; i < cnt; i += blockDim.x)
        atomicAdd(&hist[(unsigned int)(g_cand[b][i] >> (32 + BIN_SHIFT))], 1u);
    __syncthreads();
    unsigned int ck = find_cut(hist, chunk, suff, &cut_s);

    // ---- filter candidates >= cutoff into shared ----
    if (tid == 0) nkeep = 0;
    __syncthreads();
    for (int i = tid; i < cnt; i += blockDim.x) {
        unsigned long long c = g_cand[b][i];
        if ((unsigned int)(c >> 32) >= ck) {
            int p = atomicAdd(&nkeep, 1);
            if (p < KEEPMAX) arr[p] = c;
        }
    }
    __syncthreads();
    const int n = min(nkeep, KEEPMAX);

    // ---- exact rank-by-count (composites distinct -> unique ranks) ----
    for (int r = tid; r < TOPK; r += blockDim.x) topc[r] = 0ULL;
    __syncthreads();
    for (int i = tid; i < n; i += blockDim.x) {
        unsigned long long c = arr[i];
        int rank = 0;
        for (int j = 0; j < n; j++) rank += (arr[j] > c);
        if (rank < TOPK) topc[rank] = c;
    }
    __syncthreads();

    if (tid == 0) {
        float maxs = 0.f;
        if (n > 0) {
            float f = key2f((unsigned int)(topc[0] >> 32));
            maxs = 1.f / (1.f + expf(-f));
        }
        int mode; float thr = 0.1f;
        if (maxs > 0.1f) mode = 0;
        else {
            float tmp = 0.1f; mode = 2;
            while (true) {
                tmp *= 0.9f;
                if (tmp < 0.01f) { mode = 2; break; }
                if (maxs >= tmp) { mode = 1; thr = tmp; break; }
            }
        }
        mode_s = mode; thr_s = thr;
    }
    __syncthreads();

    // output layout (float32, tuple order, C-contiguous each):
    float* oBox   = out;                       // [NB][TOPK][4]
    float* oScore = out + NB * TOPK * 4;       // [NB][TOPK]
    float* oLabel = oScore + NB * TOPK;        // [NB][TOPK]
    float* oPts   = oLabel + NB * TOPK;        // [NB][TOPK][NP][2]
    float* oMask  = oPts + NB * TOPK * NP * 2; // [NB][TOPK]

    for (int r = tid; r < TOPK; r += blockDim.x) {
        unsigned long long c = topc[r];
        const bool valid = (r < n);
        float score = 0.f, x1 = 0.f, y1 = 0.f, x2 = 0.f, y2 = 0.f;
        int label = 0, q = 0;
        bool mask = false;
        if (valid) {
            unsigned int key = (unsigned int)(c >> 32);
            unsigned int idx = ~(unsigned int)(c & 0xFFFFFFFFu);
            float f = key2f(key);
            score = 1.f / (1.f + expf(-f));
            label = (int)(idx % NC);
            q     = (int)(idx / NC);
            const float* bb = bbox + ((size_t)b * NQ + q) * 4;
            float cx = bb[0], cy = bb[1], w = bb[2], h = bb[3];
            x1 = (cx - w * 0.5f) * 30.f - 15.f;
            y1 = (cy - h * 0.5f) * 60.f - 30.f;
            x2 = (cx + w * 0.5f) * 30.f - 15.f;
            y2 = (cy + h * 0.5f) * 60.f - 30.f;
            bool rmask = x1 >= -20.f && y1 >= -35.f && x2 >= -20.f && y2 >= -35.f
                      && x1 <=  20.f && y1 <=  35.f && x2 <=  20.f && y2 <=  35.f;
            bool tm = (mode_s == 0) ? (score > 0.1f)
                    : (mode_s == 1) ? (score >= thr_s) : true;
            mask = rmask && tm;
        }
        const size_t ob = (size_t)b * TOPK + r;
        oBox[ob * 4 + 0] = mask ? x1 : 0.f;
        oBox[ob * 4 + 1] = mask ? y1 : 0.f;
        oBox[ob * 4 + 2] = mask ? x2 : 0.f;
        oBox[ob * 4 + 3] = mask ? y2 : 0.f;
        oScore[ob] = mask ? score : 0.f;
        oLabel[ob] = mask ? (float)label : 0.f;
        oMask[ob]  = mask ? 1.f : 0.f;
        const float* pp = pts + ((size_t)b * NQ + q) * (NP * 2);
#pragma unroll
        for (int j = 0; j < NP; j++) {
            float vx = 0.f, vy = 0.f;
            if (valid) { vx = pp[2 * j]; vy = pp[2 * j + 1]; }
            vx = vx * 30.f - 15.f;
            vy = vy * 60.f - 30.f;
            oPts[ob * (NP * 2) + 2 * j]     = mask ? vx : 0.f;
            oPts[ob * (NP * 2) + 2 * j + 1] = mask ? vy : 0.f;
        }
    }

    // ---- reset counter for next graph replay (after all reads) ----
    __syncthreads();
    if (tid == 0) g_cnt[b] = 0;
}

extern "C" void kernel_launch(void* const* d_in, const int* in_sizes, int n_in,
                              void* d_out, int out_size) {
    const float* cls  = (const float*)d_in[0];   // [8,100000,10]
    const float* bbox = (const float*)d_in[1];   // [8,100000,4]
    const float* pts  = (const float*)d_in[2];   // [8,100000,20,2]
    float* out = (float*)d_out;

    scan_k<<<1184, 256>>>(cls);                  // 8 blocks/SM x 148 SMs
    final_k<<<NB, 512>>>(cls, bbox, pts, out);
}